// round 7
// baseline (speedup 1.0000x reference)
#include <cuda_runtime.h>
#include <cuda_fp16.h>
#include <cstdint>

#define RES    300
#define NCOMP  48
#define NFEAT  27
#define KTOT   144
#define NPTS_BLK 256
#define THREADS  768
#define WPAD   28

#define FROWB  304                          // f row stride bytes (144*2=288 used; 304=19*16, conflict-free)
#define F_OFF    0
#define F_BYTES  (NPTS_BLK * FROWB)         // 77824
#define W_OFF    F_BYTES
#define W_BYTES  (KTOT * WPAD * 4)          // 16128
#define XYZ_OFF  (W_OFF + W_BYTES)
#define XYZ_BYTES (NPTS_BLK * 3 * 4)        // 3072
#define SMEM_DYN (XYZ_OFF + XYZ_BYTES)      // 97024 B  -> 2 CTAs/SM
#define PSTRIDE  120                        // partial slot stride (bank-conflict-free)

// Scratch: channel-last transposed fp16 copies.
__device__ __align__(16) __half g_planesH[3u * RES * RES * NCOMP]; // [i][y][x][c]
__device__ __align__(16) __half g_linesH [3u * RES * NCOMP];       // [i][r][c]

// ---------------------------------------------------------------------------
__global__ void transpose_planes_kernel(const float* __restrict__ planes) {
    __shared__ float tile[NCOMP][33];
    const int i  = blockIdx.z;
    const int y  = blockIdx.y;
    const int xt = blockIdx.x * 32;
    const int t  = threadIdx.x;
    const int tx = t & 31;
    const int tc = t >> 5;
    const int x  = xt + tx;
    #pragma unroll
    for (int r = 0; r < 6; r++) {
        const int c = tc + 8 * r;
        if (x < RES)
            tile[c][tx] = planes[(((size_t)i * NCOMP + c) * RES + y) * RES + x];
    }
    __syncthreads();
    const int nx = min(32, RES - xt);
    __half* outb = g_planesH + (((size_t)i * RES + y) * RES + xt) * NCOMP;
    for (int e = t; e < nx * NCOMP; e += 256) {
        const int xl = e / NCOMP;
        const int c  = e - xl * NCOMP;
        outb[e] = __float2half(tile[c][xl]);
    }
}

__global__ void transpose_lines_kernel(const float* __restrict__ lines) {
    const int e = blockIdx.x * 256 + threadIdx.x;
    if (e >= 3 * RES * NCOMP) return;
    const int c  = e % NCOMP;
    const int ir = e / NCOMP;
    const int r  = ir % RES;
    const int i  = ir / RES;
    g_linesH[e] = __float2half(lines[((size_t)i * NCOMP + c) * RES + r]);
}

// ---------------------------------------------------------------------------
__device__ __forceinline__ void fma2(unsigned long long& d,
                                     unsigned long long a,
                                     unsigned long long b) {
    asm("fma.rn.f32x2 %0, %1, %2, %0;" : "+l"(d) : "l"(a), "l"(b));
}
__device__ __forceinline__ unsigned long long pack2(float f) {
    unsigned long long r;
    asm("mov.b64 %0, {%1, %1};" : "=l"(r) : "f"(f));
    return r;
}
__device__ __forceinline__ float2 h2f(uint32_t u) {
    return __half22float2(*reinterpret_cast<const __half2*>(&u));
}
__device__ __forceinline__ uint32_t f2h2(float lo, float hi) {
    uint32_t r;
    asm("cvt.rn.f16x2.f32 %0, %1, %2;" : "=r"(r) : "f"(hi), "f"(lo));
    return r;
}

// ---------------------------------------------------------------------------
// Main: phase1 = 6-lane cooperative gather+interp -> fp16 f in smem;
//       phase2 = one (point, k-third) per thread; 3-way smem reduction.
// 2 CTAs/SM -> cross-CTA overlap of gather (L1tex) and matvec (FMA) phases.
// ---------------------------------------------------------------------------
__global__ __launch_bounds__(THREADS, 2)
void tvm_main_kernel(const float* __restrict__ xyz,
                     const float* __restrict__ basisW,
                     float* __restrict__ out,
                     int npts) {
    extern __shared__ char sm[];
    float* sW   = reinterpret_cast<float*>(sm + W_OFF);
    float* sXYZ = reinterpret_cast<float*>(sm + XYZ_OFF);

    const int tid  = threadIdx.x;
    const int base = blockIdx.x * NPTS_BLK;

    // Stage W [k][28] (zero pad col) and clamped xyz.
    for (int e = tid; e < KTOT * WPAD; e += THREADS) {
        const int k = e / WPAD;
        const int j = e - k * WPAD;
        sW[e] = (j < NFEAT) ? basisW[j * KTOT + k] : 0.0f;
    }
    for (int e = tid; e < NPTS_BLK * 3; e += THREADS) {
        const int p = e / 3;
        const int c = e - p * 3;
        sXYZ[e] = xyz[(size_t)min(base + p, npts - 1) * 3 + c];
    }
    __syncthreads();

    // ---------------- Phase 1: gather + interp (256 pts x 6 lanes = 2 iters) ----
    #pragma unroll 1
    for (int it = 0; it < 2; it++) {
        const int s   = tid + it * THREADS;     // 0..1535
        const int p   = s / 6;
        const int c16 = s - p * 6;
        const int co  = c16 * 8;

        const float p0 = sXYZ[p * 3 + 0];
        const float p1 = sXYZ[p * 3 + 1];
        const float p2 = sXYZ[p * 3 + 2];

        #pragma unroll
        for (int i = 0; i < 3; i++) {
            float gx, gy, gz;
            if (i == 0)      { gx = p2; gy = p1; gz = p0; }
            else if (i == 1) { gx = p2; gy = p0; gz = p1; }
            else             { gx = p1; gy = p0; gz = p2; }

            const float sc = 0.5f * (float)(RES - 1);
            const float x = (gx + 1.0f) * sc, y = (gy + 1.0f) * sc, z = (gz + 1.0f) * sc;
            const float xf = floorf(x), yf = floorf(y), zf = floorf(z);
            const float wx = x - xf, wy = y - yf, wz = z - zf;
            const int x0 = min(max((int)xf, 0), RES - 1); const int x1 = min(x0 + 1, RES - 1);
            const int y0 = min(max((int)yf, 0), RES - 1); const int y1 = min(y0 + 1, RES - 1);
            const int z0 = min(max((int)zf, 0), RES - 1); const int z1 = min(z0 + 1, RES - 1);
            const float w00 = (1.0f - wx) * (1.0f - wy);
            const float w01 = wx * (1.0f - wy);
            const float w10 = (1.0f - wx) * wy;
            const float w11 = wx * wy;
            const float lw0 = 1.0f - wz, lw1 = wz;

            const __half* P = g_planesH + (size_t)i * RES * RES * NCOMP;
            const __half* L = g_linesH  + (size_t)i * RES * NCOMP;
            const uint4 t00 = *(const uint4*)(P + ((size_t)y0 * RES + x0) * NCOMP + co);
            const uint4 t01 = *(const uint4*)(P + ((size_t)y0 * RES + x1) * NCOMP + co);
            const uint4 t10 = *(const uint4*)(P + ((size_t)y1 * RES + x0) * NCOMP + co);
            const uint4 t11 = *(const uint4*)(P + ((size_t)y1 * RES + x1) * NCOMP + co);
            const uint4 tL0 = *(const uint4*)(L + (size_t)z0 * NCOMP + co);
            const uint4 tL1 = *(const uint4*)(L + (size_t)z1 * NCOMP + co);

            const uint32_t* a00 = &t00.x; const uint32_t* a01 = &t01.x;
            const uint32_t* a10 = &t10.x; const uint32_t* a11 = &t11.x;
            const uint32_t* aL0 = &tL0.x; const uint32_t* aL1 = &tL1.x;
            uint32_t fw[4];
            #pragma unroll
            for (int w = 0; w < 4; w++) {
                const float2 v00 = h2f(a00[w]), v01 = h2f(a01[w]);
                const float2 v10 = h2f(a10[w]), v11 = h2f(a11[w]);
                const float2 L0  = h2f(aL0[w]), L1  = h2f(aL1[w]);
                const float pf0 = w00*v00.x + w01*v01.x + w10*v10.x + w11*v11.x;
                const float pf1 = w00*v00.y + w01*v01.y + w10*v10.y + w11*v11.y;
                const float lf0 = lw0*L0.x + lw1*L1.x;
                const float lf1 = lw0*L0.y + lw1*L1.y;
                fw[w] = f2h2(pf0 * lf0, pf1 * lf1);
            }
            *reinterpret_cast<uint4*>(sm + F_OFF + (size_t)p * FROWB + (i * NCOMP + co) * 2) =
                make_uint4(fw[0], fw[1], fw[2], fw[3]);
        }
    }
    __syncthreads();

    // ---------------- Phase 2: matvec, 1 point x 1 k-third per thread ----------
    const int pp = tid & 255;          // point id
    const int kt = tid >> 8;           // 0..2 (k third) -- warp-uniform

    unsigned long long acc[14];
    #pragma unroll
    for (int q = 0; q < 14; q++) acc[q] = 0ull;

    const char* row = sm + F_OFF + (size_t)pp * FROWB;
    const int kbase = kt * NCOMP;

    #pragma unroll 1
    for (int c8 = 0; c8 < 6; c8++) {   // 8 channels per chunk
        const uint4 hh = *reinterpret_cast<const uint4*>(row + (kbase + c8 * 8) * 2);
        const uint32_t* qa = &hh.x;
        #pragma unroll
        for (int w = 0; w < 4; w++) {  // channel pair
            const int k0 = kbase + c8 * 8 + 2 * w;
            const float2 fa = h2f(qa[w]);
            const unsigned long long f0 = pack2(fa.x), f1 = pack2(fa.y);
            const ulonglong2* w0 = reinterpret_cast<const ulonglong2*>(sW + k0 * WPAD);
            const ulonglong2* w1 = reinterpret_cast<const ulonglong2*>(sW + (k0 + 1) * WPAD);
            #pragma unroll
            for (int q = 0; q < 7; q++) {
                const ulonglong2 W0 = w0[q];
                fma2(acc[2*q],   W0.x, f0);
                fma2(acc[2*q+1], W0.y, f0);
                const ulonglong2 W1 = w1[q];
                fma2(acc[2*q],   W1.x, f1);
                fma2(acc[2*q+1], W1.y, f1);
            }
        }
    }
    __syncthreads();   // f reads done; F region reusable for partials

    // partials: kt 1,2 write; kt 0 reduces
    if (kt > 0) {
        unsigned long long* slot = reinterpret_cast<unsigned long long*>(
            sm + ((size_t)((kt - 1) * 256 + pp)) * PSTRIDE);
        #pragma unroll
        for (int q = 0; q < 14; q++) slot[q] = acc[q];
    }
    __syncthreads();
    if (kt == 0) {
        const float* s1 = reinterpret_cast<const float*>(sm + (size_t)pp * PSTRIDE);
        const float* s2 = reinterpret_cast<const float*>(sm + (size_t)(256 + pp) * PSTRIDE);
        float fin[28];
        #pragma unroll
        for (int q = 0; q < 14; q++) {
            float lo, hi;
            asm("mov.b64 {%0, %1}, %2;" : "=f"(lo), "=f"(hi) : "l"(acc[q]));
            fin[2*q]     = lo + s1[2*q]     + s2[2*q];
            fin[2*q + 1] = hi + s1[2*q + 1] + s2[2*q + 1];
        }
        float* dst = reinterpret_cast<float*>(sm + (size_t)pp * PSTRIDE);
        #pragma unroll
        for (int q = 0; q < 28; q++) dst[q] = fin[q];
    }
    __syncthreads();

    // coalesced store
    for (int e = tid; e < NPTS_BLK * NFEAT; e += THREADS) {
        const int pt = e / NFEAT;
        const int j  = e - pt * NFEAT;
        if (base + pt < npts)
            out[(size_t)(base + pt) * NFEAT + j] =
                *reinterpret_cast<const float*>(sm + (size_t)pt * PSTRIDE + j * 4);
    }
}

// ---------------------------------------------------------------------------
extern "C" void kernel_launch(void* const* d_in, const int* in_sizes, int n_in,
                              void* d_out, int out_size) {
    const float* xyz    = (const float*)d_in[0];
    const float* planes = (const float*)d_in[1];
    const float* lines  = (const float*)d_in[2];
    const float* basisW = (const float*)d_in[3];
    float* out = (float*)d_out;
    const int npts = in_sizes[0] / 3;

    cudaFuncSetAttribute(tvm_main_kernel,
                         cudaFuncAttributeMaxDynamicSharedMemorySize, SMEM_DYN);

    dim3 tg((RES + 31) / 32, RES, 3);
    transpose_planes_kernel<<<tg, 256>>>(planes);
    transpose_lines_kernel<<<(3 * RES * NCOMP + 255) / 256, 256>>>(lines);
    const int nblk = (npts + NPTS_BLK - 1) / NPTS_BLK;
    tvm_main_kernel<<<nblk, THREADS, SMEM_DYN>>>(xyz, basisW, out, npts);
}

// round 8
// speedup vs baseline: 1.5846x; 1.5846x over previous
#include <cuda_runtime.h>
#include <cuda_fp16.h>
#include <cstdint>

#define RES    300
#define NCOMP  48
#define NFEAT  27
#define KTOT   144
#define NPTS_BLK 192
#define THREADS  384
#define WPAD   28

#define FROWB  304                          // f row stride bytes (288 used; conflict-free)
#define F_OFF    0
#define F_BYTES  (NPTS_BLK * FROWB)         // 58368
#define W_OFF    F_BYTES
#define W_BYTES  (KTOT * WPAD * 4)          // 16128
#define XYZ_OFF  (W_OFF + W_BYTES)
#define XYZ_BYTES (NPTS_BLK * 3 * 4)        // 2304
#define SMEM_DYN (XYZ_OFF + XYZ_BYTES)      // 76800 B -> 2 CTAs/SM
#define PSTRIDE  120                        // partial slot stride
#define OSTRIDE  116                        // output staging row stride (29 words, odd)
#define STG_OFF  24576                      // staging inside F region (after 192*120=23040)

// Scratch: channel-last transposed fp16 copies.
__device__ __align__(16) __half g_planesH[3u * RES * RES * NCOMP]; // [i][y][x][c]
__device__ __align__(16) __half g_linesH [3u * RES * NCOMP];       // [i][r][c]

// ---------------------------------------------------------------------------
__global__ void transpose_planes_kernel(const float* __restrict__ planes) {
    __shared__ float tile[NCOMP][33];
    const int i  = blockIdx.z;
    const int y  = blockIdx.y;
    const int xt = blockIdx.x * 32;
    const int t  = threadIdx.x;
    const int tx = t & 31;
    const int tc = t >> 5;
    const int x  = xt + tx;
    #pragma unroll
    for (int r = 0; r < 6; r++) {
        const int c = tc + 8 * r;
        if (x < RES)
            tile[c][tx] = planes[(((size_t)i * NCOMP + c) * RES + y) * RES + x];
    }
    __syncthreads();
    const int nx = min(32, RES - xt);
    __half* outb = g_planesH + (((size_t)i * RES + y) * RES + xt) * NCOMP;
    for (int e = t; e < nx * NCOMP; e += 256) {
        const int xl = e / NCOMP;
        const int c  = e - xl * NCOMP;
        outb[e] = __float2half(tile[c][xl]);
    }
}

__global__ void transpose_lines_kernel(const float* __restrict__ lines) {
    const int e = blockIdx.x * 256 + threadIdx.x;
    if (e >= 3 * RES * NCOMP) return;
    const int c  = e % NCOMP;
    const int ir = e / NCOMP;
    const int r  = ir % RES;
    const int i  = ir / RES;
    g_linesH[e] = __float2half(lines[((size_t)i * NCOMP + c) * RES + r]);
}

// ---------------------------------------------------------------------------
__device__ __forceinline__ void fma2(unsigned long long& d,
                                     unsigned long long a,
                                     unsigned long long b) {
    asm("fma.rn.f32x2 %0, %1, %2, %0;" : "+l"(d) : "l"(a), "l"(b));
}
__device__ __forceinline__ unsigned long long pack2(float f) {
    unsigned long long r;
    asm("mov.b64 %0, {%1, %1};" : "=l"(r) : "f"(f));
    return r;
}
__device__ __forceinline__ float2 h2f(uint32_t u) {
    return __half22float2(*reinterpret_cast<const __half2*>(&u));
}
__device__ __forceinline__ uint32_t f2h2(float lo, float hi) {
    uint32_t r;
    asm("cvt.rn.f16x2.f32 %0, %1, %2;" : "=r"(r) : "f"(hi), "f"(lo));
    return r;
}

// Load 7 packed W pairs (14 floats) for feature-half fh at W row base (bytes).
// fh is warp-uniform -> no divergence. fh=0: [0,56); fh=1: [56,112).
__device__ __forceinline__ void loadW7(const char* __restrict__ wrow, int fh,
                                       unsigned long long* w) {
    if (fh == 0) {
        const ulonglong2 a = *reinterpret_cast<const ulonglong2*>(wrow);
        const ulonglong2 b = *reinterpret_cast<const ulonglong2*>(wrow + 16);
        const ulonglong2 c = *reinterpret_cast<const ulonglong2*>(wrow + 32);
        const unsigned long long d = *reinterpret_cast<const unsigned long long*>(wrow + 48);
        w[0] = a.x; w[1] = a.y; w[2] = b.x; w[3] = b.y; w[4] = c.x; w[5] = c.y; w[6] = d;
    } else {
        const unsigned long long d = *reinterpret_cast<const unsigned long long*>(wrow + 56);
        const ulonglong2 a = *reinterpret_cast<const ulonglong2*>(wrow + 64);
        const ulonglong2 b = *reinterpret_cast<const ulonglong2*>(wrow + 80);
        const ulonglong2 c = *reinterpret_cast<const ulonglong2*>(wrow + 96);
        w[0] = d; w[1] = a.x; w[2] = a.y; w[3] = b.x; w[4] = b.y; w[5] = c.x; w[6] = c.y;
    }
}

// ---------------------------------------------------------------------------
// Main: phase1 = 6-lane cooperative gather+interp -> fp16 f in smem;
//       phase2 = (point-pair x feature-half x k-half) matvec; 2-way reduction.
// 76.8KB smem -> 2 CTAs/SM: gather (L1tex) and matvec (FMA) phases of the two
// CTAs overlap.
// ---------------------------------------------------------------------------
__global__ __launch_bounds__(THREADS, 2)
void tvm_main_kernel(const float* __restrict__ xyz,
                     const float* __restrict__ basisW,
                     float* __restrict__ out,
                     int npts) {
    extern __shared__ char sm[];
    float* sW   = reinterpret_cast<float*>(sm + W_OFF);
    float* sXYZ = reinterpret_cast<float*>(sm + XYZ_OFF);

    const int tid  = threadIdx.x;
    const int base = blockIdx.x * NPTS_BLK;

    for (int e = tid; e < KTOT * WPAD; e += THREADS) {
        const int k = e / WPAD;
        const int j = e - k * WPAD;
        sW[e] = (j < NFEAT) ? basisW[j * KTOT + k] : 0.0f;
    }
    for (int e = tid; e < NPTS_BLK * 3; e += THREADS) {
        const int p = e / 3;
        const int c = e - p * 3;
        sXYZ[e] = xyz[(size_t)min(base + p, npts - 1) * 3 + c];
    }
    __syncthreads();

    // ---------------- Phase 1: gather + interp (192 pts x 6 lanes = 3 iters) ----
    #pragma unroll 1
    for (int it = 0; it < 3; it++) {
        const int s   = tid + it * THREADS;     // 0..1151
        const int p   = s / 6;
        const int c16 = s - p * 6;
        const int co  = c16 * 8;

        const float p0 = sXYZ[p * 3 + 0];
        const float p1 = sXYZ[p * 3 + 1];
        const float p2 = sXYZ[p * 3 + 2];

        #pragma unroll
        for (int i = 0; i < 3; i++) {
            float gx, gy, gz;
            if (i == 0)      { gx = p2; gy = p1; gz = p0; }
            else if (i == 1) { gx = p2; gy = p0; gz = p1; }
            else             { gx = p1; gy = p0; gz = p2; }

            const float sc = 0.5f * (float)(RES - 1);
            const float x = (gx + 1.0f) * sc, y = (gy + 1.0f) * sc, z = (gz + 1.0f) * sc;
            const float xf = floorf(x), yf = floorf(y), zf = floorf(z);
            const float wx = x - xf, wy = y - yf, wz = z - zf;
            const int x0 = min(max((int)xf, 0), RES - 1); const int x1 = min(x0 + 1, RES - 1);
            const int y0 = min(max((int)yf, 0), RES - 1); const int y1 = min(y0 + 1, RES - 1);
            const int z0 = min(max((int)zf, 0), RES - 1); const int z1 = min(z0 + 1, RES - 1);
            const float w00 = (1.0f - wx) * (1.0f - wy);
            const float w01 = wx * (1.0f - wy);
            const float w10 = (1.0f - wx) * wy;
            const float w11 = wx * wy;
            const float lw0 = 1.0f - wz, lw1 = wz;

            const __half* P = g_planesH + (size_t)i * RES * RES * NCOMP;
            const __half* L = g_linesH  + (size_t)i * RES * NCOMP;
            const uint4 t00 = *(const uint4*)(P + ((size_t)y0 * RES + x0) * NCOMP + co);
            const uint4 t01 = *(const uint4*)(P + ((size_t)y0 * RES + x1) * NCOMP + co);
            const uint4 t10 = *(const uint4*)(P + ((size_t)y1 * RES + x0) * NCOMP + co);
            const uint4 t11 = *(const uint4*)(P + ((size_t)y1 * RES + x1) * NCOMP + co);
            const uint4 tL0 = *(const uint4*)(L + (size_t)z0 * NCOMP + co);
            const uint4 tL1 = *(const uint4*)(L + (size_t)z1 * NCOMP + co);

            const uint32_t* a00 = &t00.x; const uint32_t* a01 = &t01.x;
            const uint32_t* a10 = &t10.x; const uint32_t* a11 = &t11.x;
            const uint32_t* aL0 = &tL0.x; const uint32_t* aL1 = &tL1.x;
            uint32_t fw[4];
            #pragma unroll
            for (int w = 0; w < 4; w++) {
                const float2 v00 = h2f(a00[w]), v01 = h2f(a01[w]);
                const float2 v10 = h2f(a10[w]), v11 = h2f(a11[w]);
                const float2 L0  = h2f(aL0[w]), L1  = h2f(aL1[w]);
                const float pf0 = w00*v00.x + w01*v01.x + w10*v10.x + w11*v11.x;
                const float pf1 = w00*v00.y + w01*v01.y + w10*v10.y + w11*v11.y;
                const float lf0 = lw0*L0.x + lw1*L1.x;
                const float lf1 = lw0*L0.y + lw1*L1.y;
                fw[w] = f2h2(pf0 * lf0, pf1 * lf1);
            }
            *reinterpret_cast<uint4*>(sm + F_OFF + (size_t)p * FROWB + (i * NCOMP + co) * 2) =
                make_uint4(fw[0], fw[1], fw[2], fw[3]);
        }
    }
    __syncthreads();

    // ---------------- Phase 2: matvec ----------------
    // warp-uniform splits: fh = wid&1, kh = (wid>>1)&1; pair id pr = lane + 32*(wid>>2)
    const int wid  = tid >> 5;
    const int lane = tid & 31;
    const int fh   = wid & 1;
    const int kh   = (wid >> 1) & 1;
    const int pr   = lane + 32 * (wid >> 2);    // 0..95
    const int pA   = pr;
    const int pB   = pr + 96;
    const int k0   = kh * 72;

    unsigned long long accA[7], accB[7];
    #pragma unroll
    for (int q = 0; q < 7; q++) { accA[q] = 0ull; accB[q] = 0ull; }

    const char* rowA = sm + F_OFF + (size_t)pA * FROWB;
    const char* rowB = sm + F_OFF + (size_t)pB * FROWB;

    #pragma unroll 1
    for (int c8 = 0; c8 < 9; c8++) {            // 8 channels per chunk, 72 k total
        const int kc = k0 + c8 * 8;
        const uint4 hA = *reinterpret_cast<const uint4*>(rowA + kc * 2);
        const uint4 hB = *reinterpret_cast<const uint4*>(rowB + kc * 2);
        const uint32_t* qa = &hA.x;
        const uint32_t* qb = &hB.x;
        #pragma unroll
        for (int w = 0; w < 4; w++) {           // channel pair (k, k+1)
            const int k = kc + 2 * w;
            const float2 fa = h2f(qa[w]);
            const float2 fb = h2f(qb[w]);
            const unsigned long long fA0 = pack2(fa.x), fA1 = pack2(fa.y);
            const unsigned long long fB0 = pack2(fb.x), fB1 = pack2(fb.y);
            unsigned long long w0[7], w1[7];
            loadW7(reinterpret_cast<const char*>(sW + k * WPAD), fh, w0);
            loadW7(reinterpret_cast<const char*>(sW + (k + 1) * WPAD), fh, w1);
            #pragma unroll
            for (int q = 0; q < 7; q++) {
                fma2(accA[q], w0[q], fA0);
                fma2(accB[q], w0[q], fB0);
                fma2(accA[q], w1[q], fA1);
                fma2(accB[q], w1[q], fB1);
            }
        }
    }
    __syncthreads();   // all f reads done; F region reusable

    // kh=1 writes partials to slot (pr + 96*fh): 14 ull = [A 7 | B 7]
    if (kh == 1) {
        unsigned long long* slot = reinterpret_cast<unsigned long long*>(
            sm + (size_t)(pr + 96 * fh) * PSTRIDE);
        #pragma unroll
        for (int q = 0; q < 7; q++) { slot[q] = accA[q]; slot[7 + q] = accB[q]; }
    }
    __syncthreads();
    // kh=0 reduces and writes final halves to staging
    if (kh == 0) {
        const float* s1 = reinterpret_cast<const float*>(
            sm + (size_t)(pr + 96 * fh) * PSTRIDE);
        float* oA = reinterpret_cast<float*>(sm + STG_OFF + (size_t)pA * OSTRIDE) + fh * 14;
        float* oB = reinterpret_cast<float*>(sm + STG_OFF + (size_t)pB * OSTRIDE) + fh * 14;
        #pragma unroll
        for (int q = 0; q < 7; q++) {
            float lo, hi;
            asm("mov.b64 {%0, %1}, %2;" : "=f"(lo), "=f"(hi) : "l"(accA[q]));
            oA[2 * q]     = lo + s1[2 * q];
            oA[2 * q + 1] = hi + s1[2 * q + 1];
            asm("mov.b64 {%0, %1}, %2;" : "=f"(lo), "=f"(hi) : "l"(accB[q]));
            oB[2 * q]     = lo + s1[14 + 2 * q];
            oB[2 * q + 1] = hi + s1[14 + 2 * q + 1];
        }
    }
    __syncthreads();

    // coalesced store
    for (int e = tid; e < NPTS_BLK * NFEAT; e += THREADS) {
        const int pt = e / NFEAT;
        const int j  = e - pt * NFEAT;
        if (base + pt < npts)
            out[(size_t)(base + pt) * NFEAT + j] =
                *reinterpret_cast<const float*>(sm + STG_OFF + (size_t)pt * OSTRIDE + j * 4);
    }
}

// ---------------------------------------------------------------------------
extern "C" void kernel_launch(void* const* d_in, const int* in_sizes, int n_in,
                              void* d_out, int out_size) {
    const float* xyz    = (const float*)d_in[0];
    const float* planes = (const float*)d_in[1];
    const float* lines  = (const float*)d_in[2];
    const float* basisW = (const float*)d_in[3];
    float* out = (float*)d_out;
    const int npts = in_sizes[0] / 3;

    cudaFuncSetAttribute(tvm_main_kernel,
                         cudaFuncAttributeMaxDynamicSharedMemorySize, SMEM_DYN);

    dim3 tg((RES + 31) / 32, RES, 3);
    transpose_planes_kernel<<<tg, 256>>>(planes);
    transpose_lines_kernel<<<(3 * RES * NCOMP + 255) / 256, 256>>>(lines);
    const int nblk = (npts + NPTS_BLK - 1) / NPTS_BLK;
    tvm_main_kernel<<<nblk, THREADS, SMEM_DYN>>>(xyz, basisW, out, npts);
}

// round 9
// speedup vs baseline: 2.4302x; 1.5336x over previous
#include <cuda_runtime.h>
#include <cuda_fp16.h>
#include <cstdint>

#define RES    300
#define NCOMP  48
#define NFEAT  27
#define KTOT   144
#define NPTS_BLK 192
#define THREADS  384

#define FROWB  304                          // f row stride bytes (288 used; conflict-free)
#define F_OFF    0
#define F_BYTES  (NPTS_BLK * FROWB)         // 58368
#define WH_OFF   F_BYTES                    // W fp16 tile [32 rows x 144 k], row stride 336B
#define WHROWB 336                          // 84 words == 20 mod 32 -> conflict-free ldmatrix
#define WH_BYTES (32 * WHROWB)              // 10752
#define XYZ_OFF  (WH_OFF + WH_BYTES)        // 69120
#define XYZ_BYTES (NPTS_BLK * 3 * 4)        // 2304
#define SMEM_DYN (XYZ_OFF + XYZ_BYTES)      // 71424 B -> 2 CTAs/SM easily
#define OSTRIDE  120                        // staging row stride bytes (30 words)

// Scratch: channel-last transposed fp16 copies.
__device__ __align__(16) __half g_planesH[3u * RES * RES * NCOMP]; // [i][y][x][c]
__device__ __align__(16) __half g_linesH [3u * RES * NCOMP];       // [i][r][c]

// ---------------------------------------------------------------------------
__global__ void transpose_planes_kernel(const float* __restrict__ planes) {
    __shared__ float tile[NCOMP][33];
    const int i  = blockIdx.z;
    const int y  = blockIdx.y;
    const int xt = blockIdx.x * 32;
    const int t  = threadIdx.x;
    const int tx = t & 31;
    const int tc = t >> 5;
    const int x  = xt + tx;
    #pragma unroll
    for (int r = 0; r < 6; r++) {
        const int c = tc + 8 * r;
        if (x < RES)
            tile[c][tx] = planes[(((size_t)i * NCOMP + c) * RES + y) * RES + x];
    }
    __syncthreads();
    const int nx = min(32, RES - xt);
    __half* outb = g_planesH + (((size_t)i * RES + y) * RES + xt) * NCOMP;
    for (int e = t; e < nx * NCOMP; e += 256) {
        const int xl = e / NCOMP;
        const int c  = e - xl * NCOMP;
        outb[e] = __float2half(tile[c][xl]);
    }
}

__global__ void transpose_lines_kernel(const float* __restrict__ lines) {
    const int e = blockIdx.x * 256 + threadIdx.x;
    if (e >= 3 * RES * NCOMP) return;
    const int c  = e % NCOMP;
    const int ir = e / NCOMP;
    const int r  = ir % RES;
    const int i  = ir / RES;
    g_linesH[e] = __float2half(lines[((size_t)i * NCOMP + c) * RES + r]);
}

// ---------------------------------------------------------------------------
__device__ __forceinline__ uint32_t smem_u32(const void* p) {
    uint32_t a;
    asm("{ .reg .u64 t; cvta.to.shared.u64 t, %1; cvt.u32.u64 %0, t; }"
        : "=r"(a) : "l"(p));
    return a;
}
__device__ __forceinline__ float2 h2f(uint32_t u) {
    return __half22float2(*reinterpret_cast<const __half2*>(&u));
}
__device__ __forceinline__ uint32_t f2h2(float lo, float hi) {
    uint32_t r;
    asm("cvt.rn.f16x2.f32 %0, %1, %2;" : "=r"(r) : "f"(hi), "f"(lo));
    return r;
}
__device__ __forceinline__ void ldsm_x4(uint32_t& r0, uint32_t& r1,
                                        uint32_t& r2, uint32_t& r3, uint32_t addr) {
    asm volatile("ldmatrix.sync.aligned.m8n8.x4.shared.b16 {%0,%1,%2,%3}, [%4];"
                 : "=r"(r0), "=r"(r1), "=r"(r2), "=r"(r3) : "r"(addr));
}
__device__ __forceinline__ void ldsm_x2(uint32_t& r0, uint32_t& r1, uint32_t addr) {
    asm volatile("ldmatrix.sync.aligned.m8n8.x2.shared.b16 {%0,%1}, [%2];"
                 : "=r"(r0), "=r"(r1) : "r"(addr));
}
__device__ __forceinline__ void mma16816(float* c,
                                         uint32_t a0, uint32_t a1, uint32_t a2, uint32_t a3,
                                         uint32_t b0, uint32_t b1) {
    asm volatile("mma.sync.aligned.m16n8k16.row.col.f32.f16.f16.f32 "
                 "{%0,%1,%2,%3}, {%4,%5,%6,%7}, {%8,%9}, {%0,%1,%2,%3};"
                 : "+f"(c[0]), "+f"(c[1]), "+f"(c[2]), "+f"(c[3])
                 : "r"(a0), "r"(a1), "r"(a2), "r"(a3), "r"(b0), "r"(b1));
}

// ---------------------------------------------------------------------------
// Main: phase1 = 6-lane cooperative gather+interp -> fp16 f[192x144] in smem;
//       phase2 = HMMA matvec: 12 warps x one 16-pt m-tile, K=144, N=32(pad).
// ---------------------------------------------------------------------------
__global__ __launch_bounds__(THREADS, 2)
void tvm_main_kernel(const float* __restrict__ xyz,
                     const float* __restrict__ basisW,
                     float* __restrict__ out,
                     int npts) {
    extern __shared__ char sm[];
    float* sXYZ = reinterpret_cast<float*>(sm + XYZ_OFF);
    const uint32_t sbase = smem_u32(sm);

    const int tid  = threadIdx.x;
    const int base = blockIdx.x * NPTS_BLK;

    // Stage W as fp16 [n=0..31][k=0..143], rows 27-31 zero (results discarded).
    for (int e = tid; e < WH_BYTES / 16; e += THREADS)
        *reinterpret_cast<uint4*>(sm + WH_OFF + e * 16) = make_uint4(0, 0, 0, 0);
    __syncthreads();
    for (int e = tid; e < NFEAT * KTOT; e += THREADS) {
        const int n = e / KTOT;
        const int k = e - n * KTOT;
        *reinterpret_cast<__half*>(sm + WH_OFF + n * WHROWB + k * 2) =
            __float2half(basisW[e]);
    }
    for (int e = tid; e < NPTS_BLK * 3; e += THREADS) {
        const int p = e / 3;
        const int c = e - p * 3;
        sXYZ[e] = xyz[(size_t)min(base + p, npts - 1) * 3 + c];
    }
    __syncthreads();

    // ---------------- Phase 1: gather + interp (192 pts x 6 lanes = 3 iters) ----
    #pragma unroll 1
    for (int it = 0; it < 3; it++) {
        const int s   = tid + it * THREADS;     // 0..1151
        const int p   = s / 6;
        const int c16 = s - p * 6;
        const int co  = c16 * 8;

        const float p0 = sXYZ[p * 3 + 0];
        const float p1 = sXYZ[p * 3 + 1];
        const float p2 = sXYZ[p * 3 + 2];

        #pragma unroll
        for (int i = 0; i < 3; i++) {
            float gx, gy, gz;
            if (i == 0)      { gx = p2; gy = p1; gz = p0; }
            else if (i == 1) { gx = p2; gy = p0; gz = p1; }
            else             { gx = p1; gy = p0; gz = p2; }

            const float sc = 0.5f * (float)(RES - 1);
            const float x = (gx + 1.0f) * sc, y = (gy + 1.0f) * sc, z = (gz + 1.0f) * sc;
            const float xf = floorf(x), yf = floorf(y), zf = floorf(z);
            const float wx = x - xf, wy = y - yf, wz = z - zf;
            const int x0 = min(max((int)xf, 0), RES - 1); const int x1 = min(x0 + 1, RES - 1);
            const int y0 = min(max((int)yf, 0), RES - 1); const int y1 = min(y0 + 1, RES - 1);
            const int z0 = min(max((int)zf, 0), RES - 1); const int z1 = min(z0 + 1, RES - 1);
            const float w00 = (1.0f - wx) * (1.0f - wy);
            const float w01 = wx * (1.0f - wy);
            const float w10 = (1.0f - wx) * wy;
            const float w11 = wx * wy;
            const float lw0 = 1.0f - wz, lw1 = wz;

            const __half* P = g_planesH + (size_t)i * RES * RES * NCOMP;
            const __half* L = g_linesH  + (size_t)i * RES * NCOMP;
            const uint4 t00 = *(const uint4*)(P + ((size_t)y0 * RES + x0) * NCOMP + co);
            const uint4 t01 = *(const uint4*)(P + ((size_t)y0 * RES + x1) * NCOMP + co);
            const uint4 t10 = *(const uint4*)(P + ((size_t)y1 * RES + x0) * NCOMP + co);
            const uint4 t11 = *(const uint4*)(P + ((size_t)y1 * RES + x1) * NCOMP + co);
            const uint4 tL0 = *(const uint4*)(L + (size_t)z0 * NCOMP + co);
            const uint4 tL1 = *(const uint4*)(L + (size_t)z1 * NCOMP + co);

            const uint32_t* a00 = &t00.x; const uint32_t* a01 = &t01.x;
            const uint32_t* a10 = &t10.x; const uint32_t* a11 = &t11.x;
            const uint32_t* aL0 = &tL0.x; const uint32_t* aL1 = &tL1.x;
            uint32_t fw[4];
            #pragma unroll
            for (int w = 0; w < 4; w++) {
                const float2 v00 = h2f(a00[w]), v01 = h2f(a01[w]);
                const float2 v10 = h2f(a10[w]), v11 = h2f(a11[w]);
                const float2 L0  = h2f(aL0[w]), L1  = h2f(aL1[w]);
                const float pf0 = w00*v00.x + w01*v01.x + w10*v10.x + w11*v11.x;
                const float pf1 = w00*v00.y + w01*v01.y + w10*v10.y + w11*v11.y;
                const float lf0 = lw0*L0.x + lw1*L1.x;
                const float lf1 = lw0*L0.y + lw1*L1.y;
                fw[w] = f2h2(pf0 * lf0, pf1 * lf1);
            }
            *reinterpret_cast<uint4*>(sm + F_OFF + (size_t)p * FROWB + (i * NCOMP + co) * 2) =
                make_uint4(fw[0], fw[1], fw[2], fw[3]);
        }
    }
    __syncthreads();

    // ---------------- Phase 2: HMMA matvec ----------------
    // warp w owns m-tile pts [16w, 16w+16); D[16 x 32] = f[16 x 144] @ Wh^T
    const int wid  = tid >> 5;
    const int lane = tid & 31;
    const int l16  = lane & 15;

    const uint32_t a_addr = sbase + F_OFF
        + (uint32_t)(16 * wid + l16) * FROWB + (uint32_t)(lane >> 4) * 16;
    const uint32_t b_addr = sbase + WH_OFF
        + (uint32_t)(l16 & 7) * WHROWB + (uint32_t)((l16 >> 3) & 1) * 16;

    float c[4][4];
    #pragma unroll
    for (int nt = 0; nt < 4; nt++)
        #pragma unroll
        for (int q = 0; q < 4; q++) c[nt][q] = 0.0f;

    #pragma unroll
    for (int ks = 0; ks < 9; ks++) {
        uint32_t a0, a1, a2, a3;
        ldsm_x4(a0, a1, a2, a3, a_addr + ks * 32);
        #pragma unroll
        for (int nt = 0; nt < 4; nt++) {
            uint32_t b0, b1;
            ldsm_x2(b0, b1, b_addr + (uint32_t)nt * (8 * WHROWB) + ks * 32);
            mma16816(c[nt], a0, a1, a2, a3, b0, b1);
        }
    }
    __syncthreads();   // all ldmatrix reads of F done; reuse F region for staging

    // Epilogue: stage D rows (fp32) at OSTRIDE-padded rows.
    {
        const int g = lane >> 2;
        const int t = lane & 3;
        char* stg = sm + F_OFF;
        #pragma unroll
        for (int nt = 0; nt < 4; nt++) {
            const int j0 = nt * 8 + 2 * t;
            if (j0 < 30) {
                *reinterpret_cast<float2*>(stg + (size_t)(16 * wid + g) * OSTRIDE + j0 * 4) =
                    make_float2(c[nt][0], c[nt][1]);
                *reinterpret_cast<float2*>(stg + (size_t)(16 * wid + g + 8) * OSTRIDE + j0 * 4) =
                    make_float2(c[nt][2], c[nt][3]);
            }
        }
    }
    __syncthreads();

    // coalesced store
    for (int e = tid; e < NPTS_BLK * NFEAT; e += THREADS) {
        const int pt = e / NFEAT;
        const int j  = e - pt * NFEAT;
        if (base + pt < npts)
            out[(size_t)(base + pt) * NFEAT + j] =
                *reinterpret_cast<const float*>(sm + F_OFF + (size_t)pt * OSTRIDE + j * 4);
    }
}

// ---------------------------------------------------------------------------
extern "C" void kernel_launch(void* const* d_in, const int* in_sizes, int n_in,
                              void* d_out, int out_size) {
    const float* xyz    = (const float*)d_in[0];
    const float* planes = (const float*)d_in[1];
    const float* lines  = (const float*)d_in[2];
    const float* basisW = (const float*)d_in[3];
    float* out = (float*)d_out;
    const int npts = in_sizes[0] / 3;

    cudaFuncSetAttribute(tvm_main_kernel,
                         cudaFuncAttributeMaxDynamicSharedMemorySize, SMEM_DYN);

    dim3 tg((RES + 31) / 32, RES, 3);
    transpose_planes_kernel<<<tg, 256>>>(planes);
    transpose_lines_kernel<<<(3 * RES * NCOMP + 255) / 256, 256>>>(lines);
    const int nblk = (npts + NPTS_BLK - 1) / NPTS_BLK;
    tvm_main_kernel<<<nblk, THREADS, SMEM_DYN>>>(xyz, basisW, out, npts);
}

// round 10
// speedup vs baseline: 2.6010x; 1.0703x over previous
#include <cuda_runtime.h>
#include <cuda_fp16.h>
#include <cstdint>

#define RES    300
#define NCOMP  48
#define NFEAT  27
#define KTOT   144
#define NPTS_BLK 192
#define THREADS  384

#define FROWB  304                          // f row stride bytes (288 used; conflict-free)
#define F_OFF    0
#define F_BYTES  (NPTS_BLK * FROWB)         // 58368
#define WH_OFF   F_BYTES                    // W fp16 tile [32 rows x 144 k]
#define WHROWB 336                          // 84 words == 20 mod 32 -> conflict-free ldmatrix
#define WH_BYTES (32 * WHROWB)              // 10752
#define XYZ_OFF  (WH_OFF + WH_BYTES)        // 69120
#define XYZ_BYTES (NPTS_BLK * 3 * 4)        // 2304
#define SMEM_DYN (XYZ_OFF + XYZ_BYTES)      // 71424 B -> 3 CTAs/SM (214.3KB)
#define OSTRIDE  120                        // staging row stride bytes

// Scratch: channel-last transposed fp16 copies.
__device__ __align__(16) __half g_planesH[3u * RES * RES * NCOMP]; // [i][y][x][c]
__device__ __align__(16) __half g_linesH [3u * RES * NCOMP];       // [i][r][c]

// ---------------------------------------------------------------------------
__global__ void transpose_planes_kernel(const float* __restrict__ planes) {
    __shared__ float tile[NCOMP][33];
    const int i  = blockIdx.z;
    const int y  = blockIdx.y;
    const int xt = blockIdx.x * 32;
    const int t  = threadIdx.x;
    const int tx = t & 31;
    const int tc = t >> 5;
    const int x  = xt + tx;
    #pragma unroll
    for (int r = 0; r < 6; r++) {
        const int c = tc + 8 * r;
        if (x < RES)
            tile[c][tx] = planes[(((size_t)i * NCOMP + c) * RES + y) * RES + x];
    }
    __syncthreads();
    const int nx = min(32, RES - xt);
    __half* outb = g_planesH + (((size_t)i * RES + y) * RES + xt) * NCOMP;
    for (int e = t; e < nx * NCOMP; e += 256) {
        const int xl = e / NCOMP;
        const int c  = e - xl * NCOMP;
        outb[e] = __float2half(tile[c][xl]);
    }
}

__global__ void transpose_lines_kernel(const float* __restrict__ lines) {
    const int e = blockIdx.x * 256 + threadIdx.x;
    if (e >= 3 * RES * NCOMP) return;
    const int c  = e % NCOMP;
    const int ir = e / NCOMP;
    const int r  = ir % RES;
    const int i  = ir / RES;
    g_linesH[e] = __float2half(lines[((size_t)i * NCOMP + c) * RES + r]);
}

// ---------------------------------------------------------------------------
__device__ __forceinline__ uint32_t smem_u32(const void* p) {
    uint32_t a;
    asm("{ .reg .u64 t; cvta.to.shared.u64 t, %1; cvt.u32.u64 %0, t; }"
        : "=r"(a) : "l"(p));
    return a;
}
__device__ __forceinline__ float2 h2f(uint32_t u) {
    return __half22float2(*reinterpret_cast<const __half2*>(&u));
}
__device__ __forceinline__ uint32_t f2h2(float lo, float hi) {
    uint32_t r;
    asm("cvt.rn.f16x2.f32 %0, %1, %2;" : "=r"(r) : "f"(hi), "f"(lo));
    return r;
}
__device__ __forceinline__ void ldsm_x4(uint32_t& r0, uint32_t& r1,
                                        uint32_t& r2, uint32_t& r3, uint32_t addr) {
    asm volatile("ldmatrix.sync.aligned.m8n8.x4.shared.b16 {%0,%1,%2,%3}, [%4];"
                 : "=r"(r0), "=r"(r1), "=r"(r2), "=r"(r3) : "r"(addr));
}
__device__ __forceinline__ void mma16816(float* c,
                                         uint32_t a0, uint32_t a1, uint32_t a2, uint32_t a3,
                                         uint32_t b0, uint32_t b1) {
    asm volatile("mma.sync.aligned.m16n8k16.row.col.f32.f16.f16.f32 "
                 "{%0,%1,%2,%3}, {%4,%5,%6,%7}, {%8,%9}, {%0,%1,%2,%3};"
                 : "+f"(c[0]), "+f"(c[1]), "+f"(c[2]), "+f"(c[3])
                 : "r"(a0), "r"(a1), "r"(a2), "r"(a3), "r"(b0), "r"(b1));
}

// ---------------------------------------------------------------------------
// Main: phase1 = 6-lane cooperative gather+interp (per-plane loop, low regs);
//       phase2 = HMMA matvec, B loaded via ldmatrix.x4 (2 n-tiles per LDSM).
// 56-reg cap -> 3 CTAs/SM -> 36 warps of latency cover.
// ---------------------------------------------------------------------------
__global__ __launch_bounds__(THREADS, 3)
void tvm_main_kernel(const float* __restrict__ xyz,
                     const float* __restrict__ basisW,
                     float* __restrict__ out,
                     int npts) {
    extern __shared__ char sm[];
    float* sXYZ = reinterpret_cast<float*>(sm + XYZ_OFF);
    const uint32_t sbase = smem_u32(sm);

    const int tid  = threadIdx.x;
    const int base = blockIdx.x * NPTS_BLK;

    // Stage W as fp16 [n=0..31][k=0..143], rows 27-31 zero (results discarded).
    for (int e = tid; e < WH_BYTES / 16; e += THREADS)
        *reinterpret_cast<uint4*>(sm + WH_OFF + e * 16) = make_uint4(0, 0, 0, 0);
    __syncthreads();
    for (int e = tid; e < NFEAT * KTOT; e += THREADS) {
        const int n = e / KTOT;
        const int k = e - n * KTOT;
        *reinterpret_cast<__half*>(sm + WH_OFF + n * WHROWB + k * 2) =
            __float2half(basisW[e]);
    }
    for (int e = tid; e < NPTS_BLK * 3; e += THREADS) {
        const int p = e / 3;
        const int c = e - p * 3;
        sXYZ[e] = xyz[(size_t)min(base + p, npts - 1) * 3 + c];
    }
    __syncthreads();

    // ---------------- Phase 1: gather + interp (192 pts x 6 lanes = 3 iters) ----
    #pragma unroll 1
    for (int it = 0; it < 3; it++) {
        const int s   = tid + it * THREADS;     // 0..1151
        const int p   = s / 6;
        const int c16 = s - p * 6;
        const int co  = c16 * 8;

        const float p0 = sXYZ[p * 3 + 0];
        const float p1 = sXYZ[p * 3 + 1];
        const float p2 = sXYZ[p * 3 + 2];

        #pragma unroll 1
        for (int i = 0; i < 3; i++) {          // keep 1 plane (6 loads) in flight
            const float gx = (i == 2) ? p1 : p2;
            const float gy = (i == 0) ? p1 : p0;
            const float gz = (i == 0) ? p0 : ((i == 1) ? p1 : p2);

            const float sc = 0.5f * (float)(RES - 1);
            const float x = (gx + 1.0f) * sc, y = (gy + 1.0f) * sc, z = (gz + 1.0f) * sc;
            const float xf = floorf(x), yf = floorf(y), zf = floorf(z);
            const float wx = x - xf, wy = y - yf, wz = z - zf;
            const int x0 = min(max((int)xf, 0), RES - 1); const int x1 = min(x0 + 1, RES - 1);
            const int y0 = min(max((int)yf, 0), RES - 1); const int y1 = min(y0 + 1, RES - 1);
            const int z0 = min(max((int)zf, 0), RES - 1); const int z1 = min(z0 + 1, RES - 1);
            const float w00 = (1.0f - wx) * (1.0f - wy);
            const float w01 = wx * (1.0f - wy);
            const float w10 = (1.0f - wx) * wy;
            const float w11 = wx * wy;
            const float lw0 = 1.0f - wz, lw1 = wz;

            const __half* P = g_planesH + (size_t)i * (RES * RES * NCOMP);
            const __half* L = g_linesH  + (size_t)i * (RES * NCOMP);
            const uint4 t00 = *(const uint4*)(P + ((size_t)y0 * RES + x0) * NCOMP + co);
            const uint4 t01 = *(const uint4*)(P + ((size_t)y0 * RES + x1) * NCOMP + co);
            const uint4 t10 = *(const uint4*)(P + ((size_t)y1 * RES + x0) * NCOMP + co);
            const uint4 t11 = *(const uint4*)(P + ((size_t)y1 * RES + x1) * NCOMP + co);
            const uint4 tL0 = *(const uint4*)(L + (size_t)z0 * NCOMP + co);
            const uint4 tL1 = *(const uint4*)(L + (size_t)z1 * NCOMP + co);

            const uint32_t* a00 = &t00.x; const uint32_t* a01 = &t01.x;
            const uint32_t* a10 = &t10.x; const uint32_t* a11 = &t11.x;
            const uint32_t* aL0 = &tL0.x; const uint32_t* aL1 = &tL1.x;
            uint32_t fw[4];
            #pragma unroll
            for (int w = 0; w < 4; w++) {
                const float2 v00 = h2f(a00[w]), v01 = h2f(a01[w]);
                const float2 v10 = h2f(a10[w]), v11 = h2f(a11[w]);
                const float2 L0  = h2f(aL0[w]), L1  = h2f(aL1[w]);
                const float pf0 = w00*v00.x + w01*v01.x + w10*v10.x + w11*v11.x;
                const float pf1 = w00*v00.y + w01*v01.y + w10*v10.y + w11*v11.y;
                const float lf0 = lw0*L0.x + lw1*L1.x;
                const float lf1 = lw0*L0.y + lw1*L1.y;
                fw[w] = f2h2(pf0 * lf0, pf1 * lf1);
            }
            *reinterpret_cast<uint4*>(sm + F_OFF + (size_t)p * FROWB + (i * NCOMP + co) * 2) =
                make_uint4(fw[0], fw[1], fw[2], fw[3]);
        }
    }
    __syncthreads();

    // ---------------- Phase 2: HMMA matvec ----------------
    // warp w owns pts [16w, 16w+16); D[16 x 32] = f[16 x 144] @ Wh^T
    const int wid  = tid >> 5;
    const int lane = tid & 31;
    const int l16  = lane & 15;
    const int g    = lane >> 3;                 // 0..3

    const uint32_t a_addr = sbase + F_OFF
        + (uint32_t)(16 * wid + l16) * FROWB + (uint32_t)(lane >> 4) * 16;
    // B x4: lanes 0-7 (n0-7,k0), 8-15 (n0-7,k8), 16-23 (n8-15,k0), 24-31 (n8-15,k8)
    const uint32_t b_addr = sbase + WH_OFF
        + (uint32_t)((g & 2) * 4 + (lane & 7)) * WHROWB + (uint32_t)(g & 1) * 16;

    float c[4][4];
    #pragma unroll
    for (int nt = 0; nt < 4; nt++)
        #pragma unroll
        for (int q = 0; q < 4; q++) c[nt][q] = 0.0f;

    #pragma unroll
    for (int ks = 0; ks < 9; ks++) {
        uint32_t a0, a1, a2, a3;
        ldsm_x4(a0, a1, a2, a3, a_addr + ks * 32);
        #pragma unroll
        for (int ntp = 0; ntp < 2; ntp++) {     // n-tile pair: covers 16 n-rows
            uint32_t b0, b1, b2, b3;
            ldsm_x4(b0, b1, b2, b3, b_addr + (uint32_t)ntp * (16 * WHROWB) + ks * 32);
            mma16816(c[2 * ntp],     a0, a1, a2, a3, b0, b1);
            mma16816(c[2 * ntp + 1], a0, a1, a2, a3, b2, b3);
        }
    }
    __syncthreads();   // all ldmatrix reads of F done; reuse F region for staging

    // Epilogue: stage D rows (fp32) at OSTRIDE-padded rows.
    {
        const int gq = lane >> 2;
        const int t  = lane & 3;
        char* stg = sm + F_OFF;
        #pragma unroll
        for (int nt = 0; nt < 4; nt++) {
            const int j0 = nt * 8 + 2 * t;
            if (j0 < 30) {
                *reinterpret_cast<float2*>(stg + (size_t)(16 * wid + gq) * OSTRIDE + j0 * 4) =
                    make_float2(c[nt][0], c[nt][1]);
                *reinterpret_cast<float2*>(stg + (size_t)(16 * wid + gq + 8) * OSTRIDE + j0 * 4) =
                    make_float2(c[nt][2], c[nt][3]);
            }
        }
    }
    __syncthreads();

    // coalesced store
    for (int e = tid; e < NPTS_BLK * NFEAT; e += THREADS) {
        const int pt = e / NFEAT;
        const int j  = e - pt * NFEAT;
        if (base + pt < npts)
            out[(size_t)(base + pt) * NFEAT + j] =
                *reinterpret_cast<const float*>(sm + F_OFF + (size_t)pt * OSTRIDE + j * 4);
    }
}

// ---------------------------------------------------------------------------
extern "C" void kernel_launch(void* const* d_in, const int* in_sizes, int n_in,
                              void* d_out, int out_size) {
    const float* xyz    = (const float*)d_in[0];
    const float* planes = (const float*)d_in[1];
    const float* lines  = (const float*)d_in[2];
    const float* basisW = (const float*)d_in[3];
    float* out = (float*)d_out;
    const int npts = in_sizes[0] / 3;

    cudaFuncSetAttribute(tvm_main_kernel,
                         cudaFuncAttributeMaxDynamicSharedMemorySize, SMEM_DYN);

    dim3 tg((RES + 31) / 32, RES, 3);
    transpose_planes_kernel<<<tg, 256>>>(planes);
    transpose_lines_kernel<<<(3 * RES * NCOMP + 255) / 256, 256>>>(lines);
    const int nblk = (npts + NPTS_BLK - 1) / NPTS_BLK;
    tvm_main_kernel<<<nblk, THREADS, SMEM_DYN>>>(xyz, basisW, out, npts);
}